// round 2
// baseline (speedup 1.0000x reference)
#include <cuda_runtime.h>
#include <math.h>

#define B_   8
#define C_   256
#define P_   4096          /* H*W = 64*64 */
#define CP_  1048576       /* C*P */
#define CH_  1024

/* ---------------- scratch (static device globals; no allocs) ------------- */
__device__ float  g_xqn [B_*CP_];       /* GN(x_q)  NCHW */
__device__ float  g_xkvn[B_*CP_];       /* GN(x_kv) NCHW */
__device__ float  g_xqnT[B_*CP_];       /* GN(x_q)  NHWC (gather source)    */
__device__ float  g_t1  [B_*CP_];       /* relu(conv3x3) NCHW               */
__device__ float  g_sampT[B_*CP_];      /* grid-sampled, NHWC               */
__device__ float  g_x1  [B_*CP_];       /* x_q + x_v                        */
__device__ float  g_hn  [B_*CP_];       /* GN(x1)                           */
__device__ float  g_h1  [B_*CH_*P_];    /* gelu(fc1)                        */
__device__ float  g_off [B_*2*P_];
__device__ float  g_wc  [C_*C_];        /* proj_w @ kv_w[v-half]            */
__device__ float  g_bc  [C_];
__device__ double g_sum [32];
__device__ double g_sq  [32];

/* ------------------------------- GN ------------------------------------- */
__global__ void zero_stats() {
    int i = threadIdx.x;
    if (i < 32) { g_sum[i] = 0.0; g_sq[i] = 0.0; }
}

__global__ void gn_reduce(const float* __restrict__ x, int so) {
    int b = blockIdx.y;
    const float* xb = x + (size_t)b * CP_;
    double s = 0.0, s2 = 0.0;
    for (int i = blockIdx.x * blockDim.x + threadIdx.x; i < CP_;
         i += gridDim.x * blockDim.x) {
        float v = xb[i];
        s  += (double)v;
        s2 += (double)v * (double)v;
    }
    __shared__ double sh[256], sh2[256];
    int t = threadIdx.x;
    sh[t] = s; sh2[t] = s2;
    __syncthreads();
    for (int o = 128; o > 0; o >>= 1) {
        if (t < o) { sh[t] += sh[t + o]; sh2[t] += sh2[t + o]; }
        __syncthreads();
    }
    if (t == 0) {
        atomicAdd(&g_sum[so + b], sh[0]);
        atomicAdd(&g_sq [so + b], sh2[0]);
    }
}

__global__ void gn_apply(const float* __restrict__ x, int so,
                         const float* __restrict__ w, const float* __restrict__ bb,
                         float* __restrict__ out) {
    int b = blockIdx.y;
    double mu  = g_sum[so + b] / (double)CP_;
    double var = g_sq [so + b] / (double)CP_ - mu * mu;
    float rs = rsqrtf((float)var + 1e-5f);
    float m  = (float)mu;
    const float* xb = x   + (size_t)b * CP_;
    float*       ob = out + (size_t)b * CP_;
    for (int i = blockIdx.x * blockDim.x + threadIdx.x; i < CP_;
         i += gridDim.x * blockDim.x) {
        int c = i >> 12;
        ob[i] = (xb[i] - m) * rs * w[c] + bb[c];
    }
}

/* --------------------------- NCHW -> NHWC ------------------------------- */
__global__ void transpose_cp(const float* __restrict__ in, float* __restrict__ out) {
    __shared__ float t[32][33];
    int b  = blockIdx.z;
    int p0 = blockIdx.x * 32, c0 = blockIdx.y * 32;
    const float* ib = in  + (size_t)b * CP_;
    float*       ob = out + (size_t)b * CP_;
    int tx = threadIdx.x, ty = threadIdx.y;
    for (int i = ty; i < 32; i += 8)
        t[i][tx] = ib[(size_t)(c0 + i) * P_ + p0 + tx];
    __syncthreads();
    for (int i = ty; i < 32; i += 8)
        ob[(size_t)(p0 + i) * C_ + c0 + tx] = t[tx][i];
}

/* ===================== 128x128x8 SGEMM building blocks =================== */
/* 256 threads, 8x8 accum per thread, register prefetch of next K-slab.      */

#define TILE_COMPUTE()                                                        \
    _Pragma("unroll")                                                         \
    for (int kk = 0; kk < 8; kk++) {                                          \
        float ra[8], rb[8];                                                   \
        *(float4*)&ra[0] = *(const float4*)&As[kk][ty8];                      \
        *(float4*)&ra[4] = *(const float4*)&As[kk][ty8 + 4];                  \
        *(float4*)&rb[0] = *(const float4*)&Bs[kk][tx8];                      \
        *(float4*)&rb[4] = *(const float4*)&Bs[kk][tx8 + 4];                  \
        _Pragma("unroll")                                                     \
        for (int i = 0; i < 8; i++)                                           \
            _Pragma("unroll")                                                 \
            for (int j = 0; j < 8; j++)                                       \
                acc[i][j] += ra[i] * rb[j];                                   \
    }

/* ---------------- conv3x3 implicit GEMM, M=256, N=4096/b, K=4608 -------- */
/* A = off1_w (256 x 4608 row-major); B gathered from concat(xkv_n, xq_n).   */
__global__ __launch_bounds__(256)
void conv3_gemm(const float* __restrict__ A, const float* __restrict__ bias) {
    const int K = 4608;
    __shared__ float As[8][128];
    __shared__ float Bs[8][128];
    int tid = threadIdx.x;
    int tx8 = (tid & 15) << 3, ty8 = (tid >> 4) << 3;
    int b  = blockIdx.z;
    int n0 = blockIdx.x * 128, m0 = blockIdx.y * 128;
    const float* srcA = g_xkvn + (size_t)b * CP_;
    const float* srcB = g_xqn  + (size_t)b * CP_;
    float acc[8][8] = {};

    int am = tid >> 1, akl = (tid & 1) << 2;      /* A: row m0+am, k-slot akl */
    int bkr = tid >> 5, bnb = (tid & 31) << 2;    /* B: k-row bkr, 4 n's      */

    float4 apre; float bpre[4];
    /* prefetch k0 = 0 */
    apre = *(const float4*)&A[(size_t)(m0 + am) * K + akl];
    {
        int k = bkr;
        int ci = k / 9, tap = k - ci * 9;
        int dy = tap / 3 - 1, dx = tap - (tap / 3) * 3 - 1;
        const float* s = (ci < 256) ? (srcA + (size_t)ci * P_)
                                    : (srcB + (size_t)(ci - 256) * P_);
#pragma unroll
        for (int j = 0; j < 4; j++) {
            int n = n0 + bnb + j;
            int h = (n >> 6) + dy, w = (n & 63) + dx;
            bpre[j] = ((unsigned)h < 64u && (unsigned)w < 64u)
                        ? __ldg(&s[(h << 6) + w]) : 0.f;
        }
    }

    for (int k0 = 0; k0 < K; k0 += 8) {
        As[akl + 0][am] = apre.x; As[akl + 1][am] = apre.y;
        As[akl + 2][am] = apre.z; As[akl + 3][am] = apre.w;
        *(float4*)&Bs[bkr][bnb] = *(float4*)&bpre[0];
        __syncthreads();

        if (k0 + 8 < K) {
            apre = *(const float4*)&A[(size_t)(m0 + am) * K + k0 + 8 + akl];
            int k = k0 + 8 + bkr;
            int ci = k / 9, tap = k - ci * 9;
            int dy = tap / 3 - 1, dx = tap - (tap / 3) * 3 - 1;
            const float* s = (ci < 256) ? (srcA + (size_t)ci * P_)
                                        : (srcB + (size_t)(ci - 256) * P_);
#pragma unroll
            for (int j = 0; j < 4; j++) {
                int n = n0 + bnb + j;
                int h = (n >> 6) + dy, w = (n & 63) + dx;
                bpre[j] = ((unsigned)h < 64u && (unsigned)w < 64u)
                            ? __ldg(&s[(h << 6) + w]) : 0.f;
            }
        }

        TILE_COMPUTE();
        __syncthreads();
    }

    float* ob = g_t1 + (size_t)b * CP_;
#pragma unroll
    for (int i = 0; i < 8; i++) {
        int m = m0 + ty8 + i;
        float bi = bias[m];
#pragma unroll
        for (int j0 = 0; j0 < 8; j0 += 4) {
            float4 v;
            v.x = fmaxf(acc[i][j0 + 0] + bi, 0.f);
            v.y = fmaxf(acc[i][j0 + 1] + bi, 0.f);
            v.z = fmaxf(acc[i][j0 + 2] + bi, 0.f);
            v.w = fmaxf(acc[i][j0 + 3] + bi, 0.f);
            *(float4*)&ob[(size_t)m * P_ + n0 + tx8 + j0] = v;
        }
    }
}

/* ------------- generic 128x128x8 1x1-conv GEMM over batch ---------------- */
/* y[b,m,n] = epi( bias[m] + sum_k A[m,k] * B[b;k,n] ), out NCHW.            */
/* LAYOUT 0: B[k,n] = Bp[b*bsb + k*ldb + n]  (NCHW activations)              */
/* LAYOUT 1: B[k,n] = Bp[b*bsb + n*ldb + k]  (NHWC activations)              */
/* EPI: 0 none, 2 exact gelu, 3 add residual (NCHW, same M).                 */
template<int LAYOUT, int EPI>
__global__ __launch_bounds__(256)
void gemm128(const float* __restrict__ A, int K,
             const float* __restrict__ Bp, int ldb, size_t bsb,
             const float* __restrict__ bias,
             const float* __restrict__ res, size_t rsb,
             float* __restrict__ out, size_t osb) {
    __shared__ float As[8][128];
    __shared__ float Bs[8][128];
    int tid = threadIdx.x;
    int tx8 = (tid & 15) << 3, ty8 = (tid >> 4) << 3;
    int b  = blockIdx.z;
    int n0 = blockIdx.x * 128, m0 = blockIdx.y * 128;
    const float* Bb = Bp + (size_t)b * bsb;
    float acc[8][8] = {};

    int am = tid >> 1, akl = (tid & 1) << 2;
    int bkr = tid >> 5, bnb = (tid & 31) << 2;   /* layout 0 */
    int bn  = tid >> 1, bkl = (tid & 1) << 2;    /* layout 1 */

    float4 apre, bpre;
    apre = *(const float4*)&A[(size_t)(m0 + am) * K + akl];
    if (LAYOUT == 0)
        bpre = *(const float4*)&Bb[(size_t)bkr * ldb + n0 + bnb];
    else
        bpre = *(const float4*)&Bb[(size_t)(n0 + bn) * ldb + bkl];

    for (int k0 = 0; k0 < K; k0 += 8) {
        As[akl + 0][am] = apre.x; As[akl + 1][am] = apre.y;
        As[akl + 2][am] = apre.z; As[akl + 3][am] = apre.w;
        if (LAYOUT == 0) {
            *(float4*)&Bs[bkr][bnb] = bpre;
        } else {
            Bs[bkl + 0][bn] = bpre.x; Bs[bkl + 1][bn] = bpre.y;
            Bs[bkl + 2][bn] = bpre.z; Bs[bkl + 3][bn] = bpre.w;
        }
        __syncthreads();

        if (k0 + 8 < K) {
            apre = *(const float4*)&A[(size_t)(m0 + am) * K + k0 + 8 + akl];
            if (LAYOUT == 0)
                bpre = *(const float4*)&Bb[(size_t)(k0 + 8 + bkr) * ldb + n0 + bnb];
            else
                bpre = *(const float4*)&Bb[(size_t)(n0 + bn) * ldb + k0 + 8 + bkl];
        }

        TILE_COMPUTE();
        __syncthreads();
    }

    float* ob = out + (size_t)b * osb;
    const float* rb = res + (size_t)b * rsb;
#pragma unroll
    for (int i = 0; i < 8; i++) {
        int m = m0 + ty8 + i;
        float bi = bias[m];
#pragma unroll
        for (int j0 = 0; j0 < 8; j0 += 4) {
            size_t o = (size_t)m * P_ + n0 + tx8 + j0;
            float4 v;
            v.x = acc[i][j0 + 0] + bi; v.y = acc[i][j0 + 1] + bi;
            v.z = acc[i][j0 + 2] + bi; v.w = acc[i][j0 + 3] + bi;
            if (EPI == 2) {
                v.x = 0.5f * v.x * (1.0f + erff(v.x * 0.70710678118654752f));
                v.y = 0.5f * v.y * (1.0f + erff(v.y * 0.70710678118654752f));
                v.z = 0.5f * v.z * (1.0f + erff(v.z * 0.70710678118654752f));
                v.w = 0.5f * v.w * (1.0f + erff(v.w * 0.70710678118654752f));
            }
            if (EPI == 3) {
                float4 r = *(const float4*)&rb[o];
                v.x += r.x; v.y += r.y; v.z += r.z; v.w += r.w;
            }
            *(float4*)&ob[o] = v;
        }
    }
}

/* --------------------- offset head: 256 -> 2 ----------------------------- */
__global__ void off_kernel(const float* __restrict__ w2, const float* __restrict__ b2) {
    int idx = blockIdx.x * blockDim.x + threadIdx.x;   /* B*P = 32768 */
    int b = idx >> 12, p = idx & 4095;
    const float* t = g_t1 + (size_t)b * CP_ + p;
    float s0 = 0.f, s1 = 0.f;
#pragma unroll 4
    for (int c = 0; c < 256; c++) {
        float v = __ldg(&t[(size_t)c * P_]);
        s0 += w2[c]       * v;
        s1 += w2[256 + c] * v;
    }
    g_off[b * 2 * P_ + p]      = s0 + b2[0];
    g_off[b * 2 * P_ + P_ + p] = s1 + b2[1];
}

/* ----------- combined weight:  Wc = proj_w @ kv_w[v-half] ---------------- */
__global__ void combine_w(const float* __restrict__ pw, const float* __restrict__ pb,
                          const float* __restrict__ kw, const float* __restrict__ kb) {
    int idx = blockIdx.x * blockDim.x + threadIdx.x;
    if (idx < 65536) {
        int o = idx >> 8, c = idx & 255;
        float s = 0.f;
        for (int j = 0; j < 256; j++)
            s += pw[o * 256 + j] * kw[(256 + j) * 256 + c];
        g_wc[o * 256 + c] = s;
    } else if (idx < 65536 + 256) {
        int o = idx - 65536;
        float s = pb[o];
        for (int j = 0; j < 256; j++)
            s += pw[o * 256 + j] * kb[256 + j];
        g_bc[o] = s;
    }
}

/* ----------------- bilinear grid-sample (zeros pad) ---------------------- */
__global__ void sample_kernel() {
    int gid  = blockIdx.x * blockDim.x + threadIdx.x;
    int pix  = gid >> 5;           /* one warp per pixel */
    int lane = gid & 31;
    int b = pix >> 12, p = pix & 4095;
    float ox = g_off[b * 2 * P_ + p];
    float oy = g_off[b * 2 * P_ + P_ + p];
    /* replicate the reference's off -> grid -> ix roundtrip exactly */
    float gx = ox / 63.0f * 2.0f - 1.0f;
    float gy = oy / 63.0f * 2.0f - 1.0f;
    float ix = (gx + 1.0f) * 0.5f * 63.0f;
    float iy = (gy + 1.0f) * 0.5f * 63.0f;
    float x0f = floorf(ix), y0f = floorf(iy);
    float wx1 = ix - x0f, wx0 = 1.0f - wx1;
    float wy1 = iy - y0f, wy0 = 1.0f - wy1;
    int x0 = (int)x0f,          y0 = (int)y0f;
    int x1 = (int)(x0f + 1.0f), y1 = (int)(y0f + 1.0f);
    float w00 = wy0 * wx0, w01 = wy0 * wx1, w10 = wy1 * wx0, w11 = wy1 * wx1;
    bool vx0 = (x0 >= 0 && x0 < 64), vx1 = (x1 >= 0 && x1 < 64);
    bool vy0 = (y0 >= 0 && y0 < 64), vy1 = (y1 >= 0 && y1 < 64);
    float e00 = (vy0 && vx0) ? w00 : 0.f;
    float e01 = (vy0 && vx1) ? w01 : 0.f;
    float e10 = (vy1 && vx0) ? w10 : 0.f;
    float e11 = (vy1 && vx1) ? w11 : 0.f;
    int xc0 = min(max(x0, 0), 63), xc1 = min(max(x1, 0), 63);
    int yc0 = min(max(y0, 0), 63), yc1 = min(max(y1, 0), 63);
    const float* base = g_xqnT + (size_t)b * CP_;
    const float* p00 = base + (size_t)((yc0 << 6) + xc0) * C_;
    const float* p01 = base + (size_t)((yc0 << 6) + xc1) * C_;
    const float* p10 = base + (size_t)((yc1 << 6) + xc0) * C_;
    const float* p11 = base + (size_t)((yc1 << 6) + xc1) * C_;
    float* o = g_sampT + (size_t)b * CP_ + (size_t)p * C_;
    for (int c = lane; c < C_; c += 32)
        o[c] = e00 * p00[c] + e01 * p01[c] + e10 * p10[c] + e11 * p11[c];
}

/* ------------------------------ launch ----------------------------------- */
extern "C" void kernel_launch(void* const* d_in, const int* in_sizes, int n_in,
                              void* d_out, int out_size) {
    const float* x_q    = (const float*)d_in[0];
    const float* x_kv   = (const float*)d_in[1];
    const float* n1_w   = (const float*)d_in[2];
    const float* n1_b   = (const float*)d_in[3];
    /* d_in[4], d_in[5] = q_w, q_b : dead code (softmax over singleton axis) */
    const float* kv_w   = (const float*)d_in[6];
    const float* kv_b   = (const float*)d_in[7];
    const float* off1_w = (const float*)d_in[8];
    const float* off1_b = (const float*)d_in[9];
    const float* off2_w = (const float*)d_in[10];
    const float* off2_b = (const float*)d_in[11];
    const float* proj_w = (const float*)d_in[12];
    const float* proj_b = (const float*)d_in[13];
    const float* n2_w   = (const float*)d_in[14];
    const float* n2_b   = (const float*)d_in[15];
    const float* fc1_w  = (const float*)d_in[16];
    const float* fc1_b  = (const float*)d_in[17];
    const float* fc2_w  = (const float*)d_in[18];
    const float* fc2_b  = (const float*)d_in[19];

    void *p_xqn, *p_xkvn, *p_xqnT, *p_hn, *p_h1, *p_x1, *p_sampT, *p_wc, *p_bc;
    cudaGetSymbolAddress(&p_xqn,  g_xqn);
    cudaGetSymbolAddress(&p_xkvn, g_xkvn);
    cudaGetSymbolAddress(&p_xqnT, g_xqnT);
    cudaGetSymbolAddress(&p_hn,   g_hn);
    cudaGetSymbolAddress(&p_h1,   g_h1);
    cudaGetSymbolAddress(&p_x1,   g_x1);
    cudaGetSymbolAddress(&p_sampT,g_sampT);
    cudaGetSymbolAddress(&p_wc,   g_wc);
    cudaGetSymbolAddress(&p_bc,   g_bc);

    /* GN #1 on x_q and x_kv */
    zero_stats<<<1, 64>>>();
    gn_reduce<<<dim3(64, 8), 256>>>(x_q,  0);
    gn_reduce<<<dim3(64, 8), 256>>>(x_kv, 8);
    gn_apply <<<dim3(256, 8), 256>>>(x_q,  0, n1_w, n1_b, (float*)p_xqn);
    gn_apply <<<dim3(256, 8), 256>>>(x_kv, 8, n1_w, n1_b, (float*)p_xkvn);
    transpose_cp<<<dim3(128, 8, 8), dim3(32, 8)>>>((const float*)p_xqn, (float*)p_xqnT);

    /* offsets: conv3x3+relu (implicit GEMM, 77 GFLOP), then 256->2 head */
    conv3_gemm<<<dim3(32, 2, 8), 256>>>(off1_w, off1_b);
    off_kernel<<<(B_ * P_) / 256, 256>>>(off2_w, off2_b);

    /* combined (proj @ kv_v) weights, grid-sample, v-GEMM (+x_q residual) */
    combine_w<<<(65536 + 256) / 256, 256>>>(proj_w, proj_b, kv_w, kv_b);
    sample_kernel<<<(B_ * P_ * 32) / 256, 256>>>();
    gemm128<1, 3><<<dim3(32, 2, 8), 256>>>(
        (const float*)p_wc, 256,
        (const float*)p_sampT, C_, (size_t)CP_,
        (const float*)p_bc,
        x_q, (size_t)CP_,
        (float*)p_x1, (size_t)CP_);

    /* GN #2 + MLP with residual */
    gn_reduce<<<dim3(64, 8), 256>>>((const float*)p_x1, 16);
    gn_apply <<<dim3(256, 8), 256>>>((const float*)p_x1, 16, n2_w, n2_b, (float*)p_hn);
    gemm128<0, 2><<<dim3(32, 8, 8), 256>>>(
        fc1_w, 256,
        (const float*)p_hn, P_, (size_t)CP_,
        fc1_b,
        (const float*)p_hn, (size_t)CP_,       /* unused for EPI=2 */
        (float*)p_h1, (size_t)CH_ * P_);
    gemm128<0, 3><<<dim3(32, 2, 8), 256>>>(
        fc2_w, 1024,
        (const float*)p_h1, P_, (size_t)CH_ * P_,
        fc2_b,
        (const float*)p_x1, (size_t)CP_,
        (float*)d_out, (size_t)CP_);
}

// round 8
// speedup vs baseline: 1.6606x; 1.6606x over previous
#include <cuda_runtime.h>
#include <cuda_bf16.h>
#include <mma.h>
#include <math.h>

using namespace nvcuda;

#define B_   8
#define C_   256
#define P_   4096
#define CP_  1048576
#define KC_  4608

/* ---------------- scratch (static device globals; no allocs) ------------- */
__device__ float          g_qf [B_*CP_];
__device__ __nv_bfloat16  g_qh [B_*CP_];
__device__ __nv_bfloat16  g_ql [B_*CP_];
__device__ __nv_bfloat16  g_kvh[B_*CP_];
__device__ __nv_bfloat16  g_kvl[B_*CP_];
__device__ float          g_t1 [B_*CP_];
__device__ float          g_off[B_*2*P_];
__device__ __nv_bfloat16  g_sph[B_*CP_];
__device__ __nv_bfloat16  g_spl[B_*CP_];
__device__ float          g_x1 [B_*CP_];
__device__ __nv_bfloat16  g_hnh[B_*CP_];
__device__ __nv_bfloat16  g_hnl[B_*CP_];
__device__ __nv_bfloat16  g_h1h[B_*P_*1024];
__device__ __nv_bfloat16  g_h1l[B_*P_*1024];
__device__ __nv_bfloat16  g_wrh[C_*KC_];
__device__ __nv_bfloat16  g_wrl[C_*KC_];
__device__ __nv_bfloat16  g_f1h[1024*C_];
__device__ __nv_bfloat16  g_f1l[1024*C_];
__device__ __nv_bfloat16  g_f2h[C_*1024];
__device__ __nv_bfloat16  g_f2l[C_*1024];
__device__ __nv_bfloat16  g_wch[C_*C_];
__device__ __nv_bfloat16  g_wcl[C_*C_];
__device__ float          g_bc [C_];
__device__ double         g_sum[32];
__device__ double         g_sq [32];

__device__ __forceinline__ void split2(float a, __nv_bfloat16* h, __nv_bfloat16* l) {
    __nv_bfloat16 hh = __float2bfloat16(a);
    *h = hh;
    *l = __float2bfloat16(a - __bfloat162float(hh));
}

/* ------------------------------- GN stats -------------------------------- */
__global__ void zero_stats() {
    int i = threadIdx.x;
    if (i < 32) { g_sum[i] = 0.0; g_sq[i] = 0.0; }
}

__global__ void gn_reduce(const float* x, int so, int use_x1) {
    int b = blockIdx.y;
    const float* xb = (use_x1 != 0 ? (const float*)g_x1 : x) + (size_t)b * CP_;
    double s = 0.0, s2 = 0.0;
    for (int i = blockIdx.x * blockDim.x + threadIdx.x; i < CP_;
         i += gridDim.x * blockDim.x) {
        float v = xb[i];
        s += (double)v; s2 += (double)v * (double)v;
    }
    __shared__ double sh[256];
    __shared__ double sh2[256];
    int t = threadIdx.x;
    sh[t] = s; sh2[t] = s2;
    __syncthreads();
    for (int o = 128; o > 0; o >>= 1) {
        if (t < o) { sh[t] += sh[t + o]; sh2[t] += sh2[t + o]; }
        __syncthreads();
    }
    if (t == 0) { atomicAdd(&g_sum[so + b], sh[0]); atomicAdd(&g_sq[so + b], sh2[0]); }
}

/* -------- GN apply + NCHW to NHWC transpose + bf16 hi/lo split ----------- */
__global__ void gn_apply_t(const float* x, int so,
                           const float* w, const float* bb, int dst) {
    __shared__ float t[32][33];
    int b = blockIdx.z;
    double mu  = g_sum[so + b] / (double)CP_;
    double var = g_sq [so + b] / (double)CP_ - mu * mu;
    float rs = rsqrtf((float)var + 1e-5f);
    float m  = (float)mu;
    int p0 = blockIdx.x * 32, c0 = blockIdx.y * 32;
    int tx = threadIdx.x, ty = threadIdx.y;
    const float* xb = x + (size_t)b * CP_;
    for (int i = ty; i < 32; i += 8) {
        int c = c0 + i;
        t[i][tx] = (xb[(size_t)c * P_ + p0 + tx] - m) * rs * w[c] + bb[c];
    }
    __syncthreads();
    size_t ob = (size_t)b * CP_;
    for (int i = ty; i < 32; i += 8) {
        float v = t[tx][i];
        size_t o = ob + (size_t)(p0 + i) * C_ + c0 + tx;
        if (dst == 0) {
            g_qf[o] = v;
            split2(v, &g_qh[o], &g_ql[o]);
        } else {
            split2(v, &g_kvh[o], &g_kvl[o]);
        }
    }
}

__global__ void gn2_apply(int so, const float* w, const float* bb) {
    int b = blockIdx.y;
    double mu  = g_sum[so + b] / (double)CP_;
    double var = g_sq [so + b] / (double)CP_ - mu * mu;
    float rs = rsqrtf((float)var + 1e-5f);
    float m  = (float)mu;
    const float* xb = g_x1 + (size_t)b * CP_;
    size_t ob = (size_t)b * CP_;
    for (int i = blockIdx.x * blockDim.x + threadIdx.x; i < CP_;
         i += gridDim.x * blockDim.x) {
        int c = i & 255;
        float v = (xb[i] - m) * rs * w[c] + bb[c];
        split2(v, &g_hnh[ob + i], &g_hnl[ob + i]);
    }
}

/* --------------------------- weight preparation -------------------------- */
__global__ void prep_split(const float* src, int n, int wsel) {
    int i = blockIdx.x * blockDim.x + threadIdx.x;
    if (i < n) {
        if (wsel == 1) split2(src[i], &g_f1h[i], &g_f1l[i]);
        else           split2(src[i], &g_f2h[i], &g_f2l[i]);
    }
}

__global__ void prep_conv_w(const float* src) {
    int i = blockIdx.x * blockDim.x + threadIdx.x;
    if (i < C_ * KC_) {
        int o = i / KC_, k = i - o * KC_;
        int tap = k >> 9, cc = k & 511;
        float v = src[(size_t)o * KC_ + (size_t)cc * 9 + tap];
        split2(v, &g_wrh[i], &g_wrl[i]);
    }
}

__global__ void combine_w(const float* pw, const float* pb,
                          const float* kw, const float* kb) {
    int idx = blockIdx.x * blockDim.x + threadIdx.x;
    if (idx < 65536) {
        int o = idx >> 8, c = idx & 255;
        float s = 0.f;
        for (int j = 0; j < 256; j++)
            s += pw[o * 256 + j] * kw[(256 + j) * 256 + c];
        split2(s, &g_wch[idx], &g_wcl[idx]);
    } else if (idx < 65536 + 256) {
        int o = idx - 65536;
        float s = pb[o];
        for (int j = 0; j < 256; j++)
            s += pw[o * 256 + j] * kb[256 + j];
        g_bc[o] = s;
    }
}

/* ============== split-bf16 wmma GEMM, CTA 128x128, BK=16 ================= */
/* cfg 1: v-GEMM  A=g_sp K=256,  B=g_wc, bias=g_bc, +x_q NCHW res -> g_x1   */
/* cfg 2: fc1     A=g_hn K=256,  B=g_f1 N=1024, gelu -> g_h1 hi/lo          */
/* cfg 3: fc2     A=g_h1 K=1024, B=g_f2, +g_x1 res -> out_ext NCHW          */
__global__ __launch_bounds__(256)
void gemm_wmma(int cfg, const float* bias_ext, const float* res_ext, float* out_ext) {
    __shared__ __align__(32) __nv_bfloat16 Ash[128][24];
    __shared__ __align__(32) __nv_bfloat16 Asl[128][24];
    __shared__ __align__(32) __nv_bfloat16 Bsh[128][24];
    __shared__ __align__(32) __nv_bfloat16 Bsl[128][24];
    __shared__ __align__(32) float st[8][16][20];

    int K = (cfg == 3) ? 1024 : 256;
    int N = (cfg == 2) ? 1024 : 256;
    const __nv_bfloat16* Ah;
    const __nv_bfloat16* Al;
    const __nv_bfloat16* Bh;
    const __nv_bfloat16* Bl;
    const float* bias;
    if (cfg == 1)      { Ah = g_sph; Al = g_spl; Bh = g_wch; Bl = g_wcl; bias = g_bc; }
    else if (cfg == 2) { Ah = g_hnh; Al = g_hnl; Bh = g_f1h; Bl = g_f1l; bias = bias_ext; }
    else               { Ah = g_h1h; Al = g_h1l; Bh = g_f2h; Bl = g_f2l; bias = bias_ext; }

    int tid = threadIdx.x, lane = tid & 31, wrp = tid >> 5;
    int wm = (wrp >> 2) * 64, wn = (wrp & 3) * 32;
    int b  = blockIdx.z;
    int m0 = blockIdx.x * 128, n0 = blockIdx.y * 128;
    size_t asb = (size_t)P_ * K;
    const __nv_bfloat16* Ahb = Ah + (size_t)b * asb;
    const __nv_bfloat16* Alb = Al + (size_t)b * asb;

    wmma::fragment<wmma::accumulator, 16, 16, 16, float> acc[4][2];
    for (int i = 0; i < 4; i++)
        for (int j = 0; j < 2; j++)
            wmma::fill_fragment(acc[i][j], 0.0f);

    int row = tid >> 1, c8 = (tid & 1) * 8;
    size_t aoff = (size_t)(m0 + row) * K + c8;
    size_t boff = (size_t)(n0 + row) * K + c8;

    uint4 pah = *(const uint4*)(Ahb + aoff);
    uint4 pal = *(const uint4*)(Alb + aoff);
    uint4 pbh = *(const uint4*)(Bh + boff);
    uint4 pbl = *(const uint4*)(Bl + boff);

    for (int k0 = 0;; k0 += 16) {
        *(uint4*)&Ash[row][c8] = pah;
        *(uint4*)&Asl[row][c8] = pal;
        *(uint4*)&Bsh[row][c8] = pbh;
        *(uint4*)&Bsl[row][c8] = pbl;
        __syncthreads();
        if (k0 + 16 < K) {
            pah = *(const uint4*)(Ahb + aoff + k0 + 16);
            pal = *(const uint4*)(Alb + aoff + k0 + 16);
            pbh = *(const uint4*)(Bh + boff + k0 + 16);
            pbl = *(const uint4*)(Bl + boff + k0 + 16);
        }
        wmma::fragment<wmma::matrix_b, 16, 16, 16, __nv_bfloat16, wmma::col_major> fbh0, fbh1, fbl0, fbl1;
        wmma::load_matrix_sync(fbh0, &Bsh[wn][0], 24);
        wmma::load_matrix_sync(fbh1, &Bsh[wn + 16][0], 24);
        wmma::load_matrix_sync(fbl0, &Bsl[wn][0], 24);
        wmma::load_matrix_sync(fbl1, &Bsl[wn + 16][0], 24);
        for (int i = 0; i < 4; i++) {
            wmma::fragment<wmma::matrix_a, 16, 16, 16, __nv_bfloat16, wmma::row_major> fah, fal;
            wmma::load_matrix_sync(fah, &Ash[wm + i * 16][0], 24);
            wmma::load_matrix_sync(fal, &Asl[wm + i * 16][0], 24);
            wmma::mma_sync(acc[i][0], fah, fbh0, acc[i][0]);
            wmma::mma_sync(acc[i][0], fah, fbl0, acc[i][0]);
            wmma::mma_sync(acc[i][0], fal, fbh0, acc[i][0]);
            wmma::mma_sync(acc[i][1], fah, fbh1, acc[i][1]);
            wmma::mma_sync(acc[i][1], fah, fbl1, acc[i][1]);
            wmma::mma_sync(acc[i][1], fal, fbh1, acc[i][1]);
        }
        __syncthreads();
        if (k0 + 16 >= K) break;
    }

    int r2 = lane >> 1, cB = (lane & 1) * 8;
    for (int i = 0; i < 4; i++) {
        for (int j = 0; j < 2; j++) {
            wmma::store_matrix_sync(&st[wrp][0][0], acc[i][j], 20, wmma::mem_row_major);
            __syncwarp();
            int m = m0 + wm + i * 16 + r2;
            int n = n0 + wn + j * 16 + cB;
            for (int c = 0; c < 8; c++) {
                float v = st[wrp][r2][cB + c] + bias[n + c];
                if (cfg == 1) {
                    v += res_ext[(size_t)b * CP_ + (size_t)(n + c) * P_ + m];
                    g_x1[(size_t)b * CP_ + (size_t)m * C_ + n + c] = v;
                } else if (cfg == 2) {
                    v = 0.5f * v * (1.0f + erff(v * 0.70710678118654752f));
                    size_t o = (size_t)b * (size_t)P_ * N + (size_t)m * N + n + c;
                    split2(v, &g_h1h[o], &g_h1l[o]);
                } else {
                    v += g_x1[(size_t)b * CP_ + (size_t)m * C_ + n + c];
                    out_ext[(size_t)b * CP_ + (size_t)(n + c) * P_ + m] = v;
                }
            }
            __syncwarp();
        }
    }
}

/* ---- conv3x3 implicit GEMM (wmma), K tap-major: k = tap*512 + channel --- */
__global__ __launch_bounds__(256)
void conv_wmma(const float* bias) {
    __shared__ __align__(32) __nv_bfloat16 Ash[128][24];
    __shared__ __align__(32) __nv_bfloat16 Asl[128][24];
    __shared__ __align__(32) __nv_bfloat16 Bsh[128][24];
    __shared__ __align__(32) __nv_bfloat16 Bsl[128][24];
    __shared__ __align__(32) float st[8][16][20];

    int tid = threadIdx.x, lane = tid & 31, wrp = tid >> 5;
    int wm = (wrp >> 2) * 64, wn = (wrp & 3) * 32;
    int b  = blockIdx.z;
    int m0 = blockIdx.x * 128, n0 = blockIdx.y * 128;

    wmma::fragment<wmma::accumulator, 16, 16, 16, float> acc[4][2];
    for (int i = 0; i < 4; i++)
        for (int j = 0; j < 2; j++)
            wmma::fill_fragment(acc[i][j], 0.0f);

    int row = tid >> 1, c8 = (tid & 1) * 8;
    int pix = m0 + row, ph = pix >> 6, pw = pix & 63;
    size_t bbase = (size_t)b * CP_;
    size_t boff = (size_t)(n0 + row) * KC_ + c8;

    uint4 pah, pal, pbh, pbl;
    {
        int hh = ph - 1, ww = pw - 1;
        if (hh >= 0 && hh < 64 && ww >= 0 && ww < 64) {
            size_t s = bbase + (size_t)((hh << 6) + ww) * C_ + c8;
            pah = *(const uint4*)(g_kvh + s);
            pal = *(const uint4*)(g_kvl + s);
        } else {
            pah.x = 0u; pah.y = 0u; pah.z = 0u; pah.w = 0u;
            pal = pah;
        }
        pbh = *(const uint4*)(g_wrh + boff);
        pbl = *(const uint4*)(g_wrl + boff);
    }

    for (int k0 = 0;; k0 += 16) {
        *(uint4*)&Ash[row][c8] = pah;
        *(uint4*)&Asl[row][c8] = pal;
        *(uint4*)&Bsh[row][c8] = pbh;
        *(uint4*)&Bsl[row][c8] = pbl;
        __syncthreads();
        if (k0 + 16 < KC_) {
            int kn = k0 + 16;
            int tap = kn >> 9, cc = (kn & 511) + c8;
            int t3 = tap / 3;
            int dy = t3 - 1, dx = tap - t3 * 3 - 1;
            int hh = ph + dy, ww = pw + dx;
            if (hh >= 0 && hh < 64 && ww >= 0 && ww < 64) {
                size_t base = bbase + (size_t)((hh << 6) + ww) * C_;
                if (cc < 256) {
                    pah = *(const uint4*)(g_kvh + base + cc);
                    pal = *(const uint4*)(g_kvl + base + cc);
                } else {
                    pah = *(const uint4*)(g_qh + base + cc - 256);
                    pal = *(const uint4*)(g_ql + base + cc - 256);
                }
            } else {
                pah.x = 0u; pah.y = 0u; pah.z = 0u; pah.w = 0u;
                pal = pah;
            }
            pbh = *(const uint4*)(g_wrh + boff + kn);
            pbl = *(const uint4*)(g_wrl + boff + kn);
        }
        wmma::fragment<wmma::matrix_b, 16, 16, 16, __nv_bfloat16, wmma::col_major> fbh0, fbh1, fbl0, fbl1;
        wmma::load_matrix_sync(fbh0, &Bsh[wn][0], 24);
        wmma::load_matrix_sync(fbh1, &Bsh[wn + 16][0], 24);
        wmma::load_matrix_sync(fbl0, &Bsl[wn][0], 24);
        wmma::load_matrix_sync(fbl1, &Bsl[wn + 16][0], 24);
        for (int i = 0; i < 4; i++) {
            wmma::fragment<wmma::matrix_a, 16, 16, 16, __nv_bfloat16, wmma::row_major> fah, fal;
            wmma::load_matrix_sync(fah, &Ash[wm + i * 16][0], 24);
            wmma::load_matrix_sync(fal, &Asl[wm + i * 16][0], 24);
            wmma::mma_sync(acc[i][0], fah, fbh0, acc[i][0]);
            wmma::mma_sync(acc[i][0], fah, fbl0, acc[i][0]);
            wmma::mma_sync(acc[i][0], fal, fbh0, acc[i][0]);
            wmma::mma_sync(acc[i][1], fah, fbh1, acc[i][1]);
            wmma::mma_sync(acc[i][1], fah, fbl1, acc[i][1]);
            wmma::mma_sync(acc[i][1], fal, fbh1, acc[i][1]);
        }
        __syncthreads();
        if (k0 + 16 >= KC_) break;
    }

    int r2 = lane >> 1, cB = (lane & 1) * 8;
    for (int i = 0; i < 4; i++) {
        for (int j = 0; j < 2; j++) {
            wmma::store_matrix_sync(&st[wrp][0][0], acc[i][j], 20, wmma::mem_row_major);
            __syncwarp();
            int m = m0 + wm + i * 16 + r2;
            int n = n0 + wn + j * 16 + cB;
            for (int c = 0; c < 8; c++) {
                float v = st[wrp][r2][cB + c] + bias[n + c];
                g_t1[bbase + (size_t)m * C_ + n + c] = fmaxf(v, 0.f);
            }
            __syncwarp();
        }
    }
}

/* --------------------- offset head: 256 -> 2 (NHWC) ---------------------- */
__global__ void off_kernel(const float* w2, const float* b2) {
    int gid = blockIdx.x * blockDim.x + threadIdx.x;
    int pix = gid >> 5, lane = gid & 31;
    int b = pix >> 12, p = pix & 4095;
    const float* t = g_t1 + (size_t)b * CP_ + (size_t)p * C_;
    float s0 = 0.f, s1 = 0.f;
    for (int c0 = 0; c0 < 256; c0 += 32) {
        float v = t[c0 + lane];
        s0 += w2[c0 + lane] * v;
        s1 += w2[256 + c0 + lane] * v;
    }
    for (int o = 16; o > 0; o >>= 1) {
        s0 += __shfl_xor_sync(0xffffffffu, s0, o);
        s1 += __shfl_xor_sync(0xffffffffu, s1, o);
    }
    if (lane == 0) {
        g_off[b * 2 * P_ + p]      = s0 + b2[0];
        g_off[b * 2 * P_ + P_ + p] = s1 + b2[1];
    }
}

/* ----------------- bilinear grid-sample (zeros pad), NHWC ---------------- */
__global__ void sample_kernel() {
    int gid = blockIdx.x * blockDim.x + threadIdx.x;
    int pix = gid >> 5, lane = gid & 31;
    int b = pix >> 12, p = pix & 4095;
    float ox = g_off[b * 2 * P_ + p];
    float oy = g_off[b * 2 * P_ + P_ + p];
    float gx = ox / 63.0f * 2.0f - 1.0f;
    float gy = oy / 63.0f * 2.0f - 1.0f;
    float ix = (gx + 1.0f) * 0.5f * 63.0f;
    float iy = (gy + 1.0f) * 0.5f * 63.0f;
    float x0f = floorf(ix), y0f = floorf(iy);
    float wx1 = ix - x0f, wx0 = 1.0f - wx1;
    float wy1 = iy - y0f, wy0 = 1.0f - wy1;
    int x0 = (int)x0f,          y0 = (int)y0f;
    int x1 = (int)(x0f + 1.0f), y1 = (int)(y0f + 1.0f);
    bool vx0 = (x0 >= 0 && x0 < 64), vx1 = (x1 >= 0 && x1 < 64);
    bool vy0 = (y0 >= 0 && y0 < 64), vy1 = (y1 >= 0 && y1 < 64);
    float e00 = (vy0 && vx0) ? wy0 * wx0 : 0.f;
    float e01 = (vy0 && vx1) ? wy0 * wx1 : 0.f;
    float e10 = (vy1 && vx0) ? wy1 * wx0 : 0.f;
    float e11 = (vy1 && vx1) ? wy1 * wx1 : 0.f;
    int xc0 = min(max(x0, 0), 63), xc1 = min(max(x1, 0), 63);
    int yc0 = min(max(y0, 0), 63), yc1 = min(max(y1, 0), 63);
    const float* base = g_qf + (size_t)b * CP_;
    const float* p00 = base + (size_t)((yc0 << 6) + xc0) * C_;
    const float* p01 = base + (size_t)((yc0 << 6) + xc1) * C_;
    const float* p10 = base + (size_t)((yc1 << 6) + xc0) * C_;
    const float* p11 = base + (size_t)((yc1 << 6) + xc1) * C_;
    size_t o = (size_t)b * CP_ + (size_t)p * C_;
    for (int c = lane; c < C_; c += 32) {
        float v = e00 * p00[c] + e01 * p01[c] + e10 * p10[c] + e11 * p11[c];
        split2(v, &g_sph[o + c], &g_spl[o + c]);
    }
}

/* ------------------------------ launch ----------------------------------- */
extern "C" void kernel_launch(void* const* d_in, const int* in_sizes, int n_in,
                              void* d_out, int out_size) {
    const float* x_q    = (const float*)d_in[0];
    const float* x_kv   = (const float*)d_in[1];
    const float* n1_w   = (const float*)d_in[2];
    const float* n1_b   = (const float*)d_in[3];
    const float* kv_w   = (const float*)d_in[6];
    const float* kv_b   = (const float*)d_in[7];
    const float* off1_w = (const float*)d_in[8];
    const float* off1_b = (const float*)d_in[9];
    const float* off2_w = (const float*)d_in[10];
    const float* off2_b = (const float*)d_in[11];
    const float* proj_w = (const float*)d_in[12];
    const float* proj_b = (const float*)d_in[13];
    const float* n2_w   = (const float*)d_in[14];
    const float* n2_b   = (const float*)d_in[15];
    const float* fc1_w  = (const float*)d_in[16];
    const float* fc1_b  = (const float*)d_in[17];
    const float* fc2_w  = (const float*)d_in[18];
    const float* fc2_b  = (const float*)d_in[19];

    zero_stats<<<1, 64>>>();
    gn_reduce<<<dim3(64, 8), 256>>>(x_q,  0, 0);
    gn_reduce<<<dim3(64, 8), 256>>>(x_kv, 8, 0);
    gn_apply_t<<<dim3(128, 8, 8), dim3(32, 8)>>>(x_q,  0, n1_w, n1_b, 0);
    gn_apply_t<<<dim3(128, 8, 8), dim3(32, 8)>>>(x_kv, 8, n1_w, n1_b, 1);

    prep_conv_w<<<(C_ * KC_ + 255) / 256, 256>>>(off1_w);
    prep_split<<<(1024 * C_ + 255) / 256, 256>>>(fc1_w, 1024 * C_, 1);
    prep_split<<<(C_ * 1024 + 255) / 256, 256>>>(fc2_w, C_ * 1024, 2);
    combine_w<<<(65536 + 256 + 255) / 256, 256>>>(proj_w, proj_b, kv_w, kv_b);

    conv_wmma<<<dim3(32, 2, 8), 256>>>(off1_b);
    off_kernel<<<(B_ * P_ * 32) / 256, 256>>>(off2_w, off2_b);

    sample_kernel<<<(B_ * P_ * 32) / 256, 256>>>();
    gemm_wmma<<<dim3(32, 2, 8), 256>>>(1, (const float*)0, x_q, (float*)0);

    gn_reduce<<<dim3(64, 8), 256>>>((const float*)0, 16, 1);
    gn2_apply<<<dim3(512, 8), 256>>>(16, n2_w, n2_b);
    gemm_wmma<<<dim3(32, 8, 8), 256>>>(2, fc1_b, (const float*)0, (float*)0);
    gemm_wmma<<<dim3(32, 2, 8), 256>>>(3, fc2_b, (const float*)0, (float*)d_out);
}